// round 1
// baseline (speedup 1.0000x reference)
#include <cuda_runtime.h>
#include <math.h>

#define MTOT 16384   // B*L = 8*2048
#define DMOD 512
#define HIN  128
#define LSEQ 2048
#define NBATCH 8

#define BM 64
#define BN 64
#define BKT 16

// ---------------- scratch (static device globals: allocation-free) ----------------
__device__ float g_h1 [MTOT*DMOD];
__device__ float g_skip[MTOT*DMOD];
__device__ float g_hn [MTOT*DMOD];
__device__ float g_bur[MTOT*DMOD];
__device__ float g_bui[MTOT*DMOD];
__device__ float g_xsr[MTOT*DMOD];
__device__ float g_xsi[MTOT*DMOD];
__device__ float g_y  [MTOT*DMOD];
__device__ float g_g1 [MTOT*DMOD];
__device__ float g_g2 [MTOT*DMOD];
__device__ float g_r  [MTOT*DMOD];
__device__ float g_hd [MTOT*DMOD];

__device__ __forceinline__ float gelu_f(float x){
    float x3 = x*x*x;
    float t = tanhf(0.7978845608028654f*(x + 0.044715f*x3));
    return 0.5f*x*(1.0f+t);
}
__device__ __forceinline__ float sigmoid_f(float x){ return 1.0f/(1.0f+expf(-x)); }

// ---------------- SGEMM: Y = A @ W^T [- A2 @ W2^T] (+bias | +D*hn then gelu) ------
// EPI=0: v = acc + (bias?bias[col]:0)
// EPI=1: dual pass (A,W) minus (A2,W2); v = gelu(acc + Dv[col]*hn[row,col])
template<int EPI>
__global__ __launch_bounds__(256)
void sgemm_k(const float* __restrict__ A, const float* __restrict__ W,
             const float* __restrict__ bias,
             const float* __restrict__ A2, const float* __restrict__ W2,
             const float* __restrict__ hn, const float* __restrict__ Dv,
             float* __restrict__ Y, int M, int N, int K)
{
    __shared__ float As[BKT][BM+4];   // row stride 68 floats (16B aligned rows)
    __shared__ float Ws[BKT][BN+4];

    const int bm = blockIdx.y * BM;
    const int bn = blockIdx.x * BN;
    const int t  = threadIdx.x;
    const int m_ld = t & 63;          // which row of the 64-row tile this thread loads
    const int q4   = (t >> 6) * 4;    // which k-quad (0,4,8,12)
    const int tx = t & 15;
    const int ty = t >> 4;

    float acc[4][4];
    #pragma unroll
    for (int i=0;i<4;i++)
        #pragma unroll
        for (int j=0;j<4;j++) acc[i][j]=0.0f;

    const int npass = (EPI==1) ? 2 : 1;
    for (int pass=0; pass<npass; ++pass) {
        const float* Ap = pass ? A2 : A;
        const float* Wp = pass ? W2 : W;
        const float sgn = pass ? -1.0f : 1.0f;
        for (int k0=0; k0<K; k0+=BKT) {
            float4 av = *(const float4*)&Ap[(size_t)(bm+m_ld)*K + k0 + q4];
            float4 wv = *(const float4*)&Wp[(size_t)(bn+m_ld)*K + k0 + q4];
            __syncthreads();
            As[q4+0][m_ld]=av.x*sgn; As[q4+1][m_ld]=av.y*sgn;
            As[q4+2][m_ld]=av.z*sgn; As[q4+3][m_ld]=av.w*sgn;
            Ws[q4+0][m_ld]=wv.x; Ws[q4+1][m_ld]=wv.y;
            Ws[q4+2][m_ld]=wv.z; Ws[q4+3][m_ld]=wv.w;
            __syncthreads();
            #pragma unroll
            for (int kk=0; kk<BKT; ++kk) {
                float4 w = *(const float4*)&Ws[kk][tx*4];
                float a0 = As[kk][ty*4+0];
                float a1 = As[kk][ty*4+1];
                float a2 = As[kk][ty*4+2];
                float a3 = As[kk][ty*4+3];
                acc[0][0]+=a0*w.x; acc[0][1]+=a0*w.y; acc[0][2]+=a0*w.z; acc[0][3]+=a0*w.w;
                acc[1][0]+=a1*w.x; acc[1][1]+=a1*w.y; acc[1][2]+=a1*w.z; acc[1][3]+=a1*w.w;
                acc[2][0]+=a2*w.x; acc[2][1]+=a2*w.y; acc[2][2]+=a2*w.z; acc[2][3]+=a2*w.w;
                acc[3][0]+=a3*w.x; acc[3][1]+=a3*w.y; acc[3][2]+=a3*w.z; acc[3][3]+=a3*w.w;
            }
        }
    }

    #pragma unroll
    for (int i=0;i<4;i++) {
        int row = bm + ty*4 + i;
        #pragma unroll
        for (int j=0;j<4;j++) {
            int col = bn + tx*4 + j;
            float v = acc[i][j];
            if (EPI==0) {
                if (bias) v += bias[col];
            } else {
                v += Dv[col]*hn[(size_t)row*N + col];
                v = gelu_f(v);
            }
            Y[(size_t)row*N + col] = v;
        }
    }
}

// ---------------- LayerNorm over last dim (D=512), one block (128 thr) per row -----
__global__ __launch_bounds__(128)
void ln_k(const float* __restrict__ X, const float* __restrict__ g,
          const float* __restrict__ b, float* __restrict__ Y)
{
    int row = blockIdx.x;
    const float4* x4 = (const float4*)(X + (size_t)row*DMOD);
    float4 v = x4[threadIdx.x];
    float s  = v.x+v.y+v.z+v.w;
    float s2 = v.x*v.x+v.y*v.y+v.z*v.z+v.w*v.w;
    #pragma unroll
    for (int o=16;o>0;o>>=1) {
        s  += __shfl_xor_sync(0xffffffffu, s , o);
        s2 += __shfl_xor_sync(0xffffffffu, s2, o);
    }
    __shared__ float ss[4], ss2[4];
    int w = threadIdx.x >> 5;
    if ((threadIdx.x & 31)==0) { ss[w]=s; ss2[w]=s2; }
    __syncthreads();
    s  = ss[0]+ss[1]+ss[2]+ss[3];
    s2 = ss2[0]+ss2[1]+ss2[2]+ss2[3];
    float mean = s * (1.0f/DMOD);
    float var  = s2 * (1.0f/DMOD) - mean*mean;
    float inv  = rsqrtf(var + 1e-5f);
    float4 gg = ((const float4*)g)[threadIdx.x];
    float4 bb = ((const float4*)b)[threadIdx.x];
    float4 o;
    o.x = (v.x-mean)*inv*gg.x + bb.x;
    o.y = (v.y-mean)*inv*gg.y + bb.y;
    o.z = (v.z-mean)*inv*gg.z + bb.z;
    o.w = (v.w-mean)*inv*gg.w + bb.w;
    ((float4*)(Y + (size_t)row*DMOD))[threadIdx.x] = o;
}

// ---------------- LinOSS IM scan: one thread per (re/im, b, n), sequential in L ----
__global__ __launch_bounds__(128)
void scan_k(const float* __restrict__ bur, const float* __restrict__ bui,
            float* __restrict__ xsr, float* __restrict__ xsi,
            const float* __restrict__ A_diag, const float* __restrict__ log_steps)
{
    int idx  = blockIdx.x*128 + threadIdx.x;   // 0..8191
    int n    = idx & 511;
    int b    = (idx >> 9) & 7;
    int part = idx >> 12;                       // 0 = real, 1 = imag

    float A   = fmaxf(A_diag[n], 0.0f);
    float dt  = sigmoid_f(log_steps[n]);
    float dtA = dt*dt*A;
    float S   = 1.0f/(1.0f+dtA);
    float m11 = 1.0f - dtA*S;
    float m12 = -dt*A*S;
    float m21 = dt*S;
    float m22 = S;
    float cz  = m11*dt;
    float cx  = m21*dt;

    const float* bu = (part ? bui : bur) + (size_t)b*LSEQ*DMOD + n;
    float*       xs = (part ? xsi : xsr) + (size_t)b*LSEQ*DMOD + n;

    float z = 0.0f, x = 0.0f;
    for (int l=0; l<LSEQ; l+=8) {
        float v[8];
        #pragma unroll
        for (int u=0;u<8;u++) v[u] = __ldg(&bu[(size_t)(l+u)*DMOD]);
        #pragma unroll
        for (int u=0;u<8;u++) {
            float zn = fmaf(m11, z, fmaf(m12, x, cz*v[u]));
            float xn = fmaf(m21, z, fmaf(m22, x, cx*v[u]));
            z = zn; x = xn;
            xs[(size_t)(l+u)*DMOD] = x;
        }
    }
}

// ---------------- GLU combine + residual: r = skip + g1 * sigmoid(g2) --------------
__global__ __launch_bounds__(256)
void glu_res_k(const float* __restrict__ skip, const float* __restrict__ a,
               const float* __restrict__ bgate, float* __restrict__ r, int n4)
{
    int i = blockIdx.x*blockDim.x + threadIdx.x;
    if (i >= n4) return;
    float4 s  = ((const float4*)skip )[i];
    float4 av = ((const float4*)a    )[i];
    float4 gv = ((const float4*)bgate)[i];
    float4 o;
    o.x = s.x + av.x*sigmoid_f(gv.x);
    o.y = s.y + av.y*sigmoid_f(gv.y);
    o.z = s.z + av.z*sigmoid_f(gv.z);
    o.w = s.w + av.w*sigmoid_f(gv.w);
    ((float4*)r)[i] = o;
}

// ---------------- host launcher ----------------------------------------------------
static float* symaddr(const void* sym) {
    void* p = nullptr;
    cudaGetSymbolAddress(&p, sym);
    return (float*)p;
}

extern "C" void kernel_launch(void* const* d_in, const int* in_sizes, int n_in,
                              void* d_out, int out_size)
{
    const float* x      = (const float*)d_in[0];
    const float* W_in   = (const float*)d_in[1];
    const float* b_in   = (const float*)d_in[2];
    const float* W_enc  = (const float*)d_in[3];
    const float* b_enc  = (const float*)d_in[4];
    const float* ln_g   = (const float*)d_in[5];
    const float* ln_b   = (const float*)d_in[6];
    const float* A_diag = (const float*)d_in[7];
    const float* log_st = (const float*)d_in[8];
    const float* B_re   = (const float*)d_in[9];
    const float* B_im   = (const float*)d_in[10];
    const float* C_re   = (const float*)d_in[11];
    const float* C_im   = (const float*)d_in[12];
    const float* Dvec   = (const float*)d_in[13];
    const float* glu_w1 = (const float*)d_in[14];
    const float* glu_b1 = (const float*)d_in[15];
    const float* glu_w2 = (const float*)d_in[16];
    const float* glu_b2 = (const float*)d_in[17];
    const float* W_dec  = (const float*)d_in[18];
    const float* b_dec  = (const float*)d_in[19];
    const float* W_out  = (const float*)d_in[20];
    const float* b_out  = (const float*)d_in[21];
    float* out = (float*)d_out;

    float* h1   = symaddr(g_h1);
    float* skip = symaddr(g_skip);
    float* hn   = symaddr(g_hn);
    float* bur  = symaddr(g_bur);
    float* bui  = symaddr(g_bui);
    float* xsr  = symaddr(g_xsr);
    float* xsi  = symaddr(g_xsi);
    float* y    = symaddr(g_y);
    float* gg1  = symaddr(g_g1);
    float* gg2  = symaddr(g_g2);
    float* r    = symaddr(g_r);
    float* hd   = symaddr(g_hd);

    dim3 gD(DMOD/BN, MTOT/BM);   // (8, 256) for N=512 GEMMs
    dim3 gO(HIN /BN, MTOT/BM);   // (2, 256) for the final N=128 GEMM

    // 1) h1 = x @ W_in^T + b_in          (K=128)
    sgemm_k<0><<<gD, 256>>>(x, W_in, b_in, nullptr,nullptr,nullptr,nullptr,
                            h1, MTOT, DMOD, HIN);
    // 2) skip = h1 @ W_enc^T + b_enc     (K=512)
    sgemm_k<0><<<gD, 256>>>(h1, W_enc, b_enc, nullptr,nullptr,nullptr,nullptr,
                            skip, MTOT, DMOD, DMOD);
    // 3) hn = layernorm(skip)
    ln_k<<<MTOT, 128>>>(skip, ln_g, ln_b, hn);
    // 4) Bu = hn @ (B_re + i B_im)^T
    sgemm_k<0><<<gD, 256>>>(hn, B_re, nullptr, nullptr,nullptr,nullptr,nullptr,
                            bur, MTOT, DMOD, DMOD);
    sgemm_k<0><<<gD, 256>>>(hn, B_im, nullptr, nullptr,nullptr,nullptr,nullptr,
                            bui, MTOT, DMOD, DMOD);
    // 5) xs = linoss_scan_im(A, dt, Bu)
    scan_k<<<64, 128>>>(bur, bui, xsr, xsi, A_diag, log_st);
    // 6) y = gelu(xsr@C_re^T - xsi@C_im^T + D*hn)
    sgemm_k<1><<<gD, 256>>>(xsr, C_re, nullptr, xsi, C_im, hn, Dvec,
                            y, MTOT, DMOD, DMOD);
    // 7) GLU branches
    sgemm_k<0><<<gD, 256>>>(y, glu_w1, glu_b1, nullptr,nullptr,nullptr,nullptr,
                            gg1, MTOT, DMOD, DMOD);
    sgemm_k<0><<<gD, 256>>>(y, glu_w2, glu_b2, nullptr,nullptr,nullptr,nullptr,
                            gg2, MTOT, DMOD, DMOD);
    // 8) r = skip + gg1 * sigmoid(gg2)
    int n4 = MTOT*DMOD/4;
    glu_res_k<<<(n4+255)/256, 256>>>(skip, gg1, gg2, r, n4);
    // 9) hd = r @ W_dec^T + b_dec
    sgemm_k<0><<<gD, 256>>>(r, W_dec, b_dec, nullptr,nullptr,nullptr,nullptr,
                            hd, MTOT, DMOD, DMOD);
    // 10) out = hd @ W_out^T + b_out     (N=128)
    sgemm_k<0><<<gO, 256>>>(hd, W_out, b_out, nullptr,nullptr,nullptr,nullptr,
                            out, MTOT, HIN, DMOD);
}

// round 6
// speedup vs baseline: 1.6945x; 1.6945x over previous
#include <cuda_runtime.h>
#include <cuda_bf16.h>
#include <math.h>
#include <stdint.h>

#define MTOT 16384   // B*L
#define DMOD 512
#define HIN  128
#define LSEQ 2048

// ---------------- scratch (static device globals: allocation-free) ----------------
__device__ float g_skip[MTOT*DMOD];
__device__ float g_hn  [MTOT*DMOD];
__device__ float g_bur [MTOT*DMOD];
__device__ float g_bui [MTOT*DMOD];
__device__ float g_g1  [MTOT*DMOD];
__device__ float g_g2  [MTOT*DMOD];

__device__ __nv_bfloat16 g_xh [MTOT*HIN],  g_xl [MTOT*HIN];
__device__ __nv_bfloat16 g_h1h[MTOT*DMOD], g_h1l[MTOT*DMOD];
__device__ __nv_bfloat16 g_hnh[MTOT*DMOD], g_hnl[MTOT*DMOD];
__device__ __nv_bfloat16 g_xsrh[MTOT*DMOD], g_xsrl[MTOT*DMOD];
__device__ __nv_bfloat16 g_xsih[MTOT*DMOD], g_xsil[MTOT*DMOD];
__device__ __nv_bfloat16 g_yh [MTOT*DMOD], g_yl [MTOT*DMOD];
__device__ __nv_bfloat16 g_rh [MTOT*DMOD], g_rl [MTOT*DMOD];
__device__ __nv_bfloat16 g_hdh[MTOT*DMOD], g_hdl[MTOT*DMOD];

// weight hi/lo pairs
__device__ __nv_bfloat16 g_Winh [DMOD*HIN],  g_Winl [DMOD*HIN];
__device__ __nv_bfloat16 g_Wench[DMOD*DMOD], g_Wencl[DMOD*DMOD];
__device__ __nv_bfloat16 g_Breh [DMOD*DMOD], g_Brel [DMOD*DMOD];
__device__ __nv_bfloat16 g_Bimh [DMOD*DMOD], g_Biml [DMOD*DMOD];
__device__ __nv_bfloat16 g_Creh [DMOD*DMOD], g_Crel [DMOD*DMOD];
__device__ __nv_bfloat16 g_Cimh [DMOD*DMOD], g_Ciml [DMOD*DMOD];  // pre-negated
__device__ __nv_bfloat16 g_W1h  [DMOD*DMOD], g_W1l  [DMOD*DMOD];
__device__ __nv_bfloat16 g_W2h  [DMOD*DMOD], g_W2l  [DMOD*DMOD];
__device__ __nv_bfloat16 g_Wdech[DMOD*DMOD], g_Wdecl[DMOD*DMOD];
__device__ __nv_bfloat16 g_Wouth[HIN*DMOD],  g_Woutl[HIN*DMOD];

__device__ __forceinline__ float gelu_f(float x){
    float x3 = x*x*x;
    float t = tanhf(0.7978845608028654f*(x + 0.044715f*x3));
    return 0.5f*x*(1.0f+t);
}
__device__ __forceinline__ float sigmoid_f(float x){ return 1.0f/(1.0f+expf(-x)); }

__device__ __forceinline__ void split_bf16(float v, __nv_bfloat16& h, __nv_bfloat16& l){
    h = __float2bfloat16(v);
    l = __float2bfloat16(v - __bfloat162float(h));
}

__device__ __forceinline__ uint32_t smem_u32(const void* p){
    uint32_t a;
    asm("{ .reg .u64 t; cvta.to.shared.u64 t, %1; cvt.u32.u64 %0, t; }" : "=r"(a) : "l"(p));
    return a;
}
__device__ __forceinline__ void cpa16(uint32_t dst, const void* src){
    asm volatile("cp.async.cg.shared.global [%0], [%1], 16;" :: "r"(dst), "l"(src));
}
__device__ __forceinline__ void cpa_commit(){ asm volatile("cp.async.commit_group;" ::: "memory"); }

__device__ __forceinline__ void ldm4(uint32_t addr, uint32_t& r0, uint32_t& r1,
                                     uint32_t& r2, uint32_t& r3){
    asm volatile("ldmatrix.sync.aligned.m8n8.x4.shared.b16 {%0,%1,%2,%3}, [%4];"
                 : "=r"(r0), "=r"(r1), "=r"(r2), "=r"(r3) : "r"(addr));
}
__device__ __forceinline__ void mma16816(float* d, uint32_t a0, uint32_t a1,
                                         uint32_t a2, uint32_t a3,
                                         uint32_t b0, uint32_t b1){
    asm volatile("mma.sync.aligned.m16n8k16.row.col.f32.bf16.bf16.f32 "
                 "{%0,%1,%2,%3}, {%4,%5,%6,%7}, {%8,%9}, {%0,%1,%2,%3};"
                 : "+f"(d[0]), "+f"(d[1]), "+f"(d[2]), "+f"(d[3])
                 : "r"(a0), "r"(a1), "r"(a2), "r"(a3), "r"(b0), "r"(b1));
}

// ---------------- mma.sync GEMM ----------------------------------------------------
// Y[M,N] = sum over passes of A_p @ B_p^T (A,B bf16 hi/lo splits, fp32 accumulate).
// EPI 0: fp32 out (+bias if nonnull). EPI 1: bf16 hi/lo out (+bias).
// EPI 2: v = gelu(acc + Dv[col]*hn[row,col]) -> bf16 hi/lo out.
#define RS   80                     // smem row stride bytes (conflict-free ldmatrix)
#define STGA (128*RS)               // 10240 per operand tile
#define STG  (2*STGA)               // 20480 per stage
#define NSTG 3
#define GSMEM_TOTAL (NSTG*STG)      // 61440

template<int EPI>
__global__ __launch_bounds__(256)
void mma_gemm(const __nv_bfloat16* __restrict__ a1h, const __nv_bfloat16* __restrict__ a1l,
              const __nv_bfloat16* __restrict__ b1h, const __nv_bfloat16* __restrict__ b1l,
              const __nv_bfloat16* __restrict__ a2h, const __nv_bfloat16* __restrict__ a2l,
              const __nv_bfloat16* __restrict__ b2h, const __nv_bfloat16* __restrict__ b2l,
              const float* __restrict__ bias, const float* __restrict__ Dv,
              const float* __restrict__ hn,
              float* __restrict__ Yf, __nv_bfloat16* __restrict__ Yh,
              __nv_bfloat16* __restrict__ Yl,
              int N, int K, int npass)
{
    extern __shared__ __align__(128) char smem[];
    uint32_t sb = smem_u32(smem);
    const int tid = threadIdx.x, wid = tid>>5, lane = tid&31;
    const int warp_m = wid & 1, warp_n = wid >> 1;
    const int bm = blockIdx.y*128, bn = blockIdx.x*128;

    const __nv_bfloat16* Al[6]; const __nv_bfloat16* Bl[6];
    Al[0]=a1h; Bl[0]=b1h;  Al[1]=a1l; Bl[1]=b1h;  Al[2]=a1h; Bl[2]=b1l;
    Al[3]=a2h; Bl[3]=b2h;  Al[4]=a2l; Bl[4]=b2h;  Al[5]=a2h; Bl[5]=b2l;

    const int kcp = K >> 5;          // 32-wide K chunks per pass
    const int nch = npass*kcp;

    const int row = tid >> 1;        // 0..127
    const int cp2 = (tid & 1)*2;     // chunk pair {0,1} or {2,3}

    float acc[4][4][4];
    #pragma unroll
    for (int i=0;i<4;i++)
        #pragma unroll
        for (int j=0;j<4;j++){ acc[i][j][0]=0.f; acc[i][j][1]=0.f; acc[i][j][2]=0.f; acc[i][j][3]=0.f; }

    // prologue: chunks 0..NSTG-2
    #pragma unroll
    for (int c=0;c<NSTG-1;c++){
        int pass = c/kcp, kc = c - pass*kcp;
        const __nv_bfloat16* As = Al[pass] + (size_t)(bm+row)*K + kc*32 + cp2*8;
        const __nv_bfloat16* Bs = Bl[pass] + (size_t)(bn+row)*K + kc*32 + cp2*8;
        uint32_t sa = sb + c*STG + row*RS + cp2*16;
        cpa16(sa,       As);
        cpa16(sa+16,    As+8);
        cpa16(sa+STGA,    Bs);
        cpa16(sa+STGA+16, Bs+8);
        cpa_commit();
    }

    // lane offsets for ldmatrix (canonical x4 mapping)
    const int lrow = (lane & 7) + ((lane >> 3) & 1)*8;  // row within 16-row group
    const int lcol = (lane >> 4)*16;                     // byte col-half

    for (int j=0;j<nch;j++){
        asm volatile("cp.async.wait_group %0;" :: "n"(NSTG-2) : "memory");
        __syncthreads();

        int c = j + NSTG - 1;
        if (c < nch){
            int pass = c/kcp, kc = c - pass*kcp;
            const __nv_bfloat16* As = Al[pass] + (size_t)(bm+row)*K + kc*32 + cp2*8;
            const __nv_bfloat16* Bs = Bl[pass] + (size_t)(bn+row)*K + kc*32 + cp2*8;
            uint32_t sa = sb + (c%NSTG)*STG + row*RS + cp2*16;
            cpa16(sa,       As);
            cpa16(sa+16,    As+8);
            cpa16(sa+STGA,    Bs);
            cpa16(sa+STGA+16, Bs+8);
        }
        cpa_commit();

        uint32_t abase = sb + (j%NSTG)*STG;
        uint32_t bbase = abase + STGA;
        #pragma unroll
        for (int ks=0; ks<2; ks++){
            uint32_t koff = ks*32 + lcol;
            uint32_t a[4][4], b[2][4];
            #pragma unroll
            for (int mt=0; mt<4; mt++){
                uint32_t ad = abase + (uint32_t)(warp_m*64 + mt*16 + lrow)*RS + koff;
                ldm4(ad, a[mt][0], a[mt][1], a[mt][2], a[mt][3]);
            }
            #pragma unroll
            for (int g=0; g<2; g++){
                uint32_t bd = bbase + (uint32_t)(warp_n*32 + g*16 + lrow)*RS + koff;
                ldm4(bd, b[g][0], b[g][1], b[g][2], b[g][3]);
            }
            #pragma unroll
            for (int mt=0; mt<4; mt++)
                #pragma unroll
                for (int nt=0; nt<4; nt++){
                    int g = nt >> 1, sub = nt & 1;
                    // regs: b[g][sub] = b0 (k0-7), b[g][sub+2] = b1 (k8-15)
                    mma16816(acc[mt][nt], a[mt][0], a[mt][1], a[mt][2], a[mt][3],
                             b[g][sub], b[g][sub+2]);
                }
        }
    }
    __syncthreads();

    // ---------------- epilogue ----------------
    const int r0l = lane >> 2;          // 0..7
    const int c0l = (lane & 3)*2;       // 0,2,4,6
    #pragma unroll
    for (int mt=0; mt<4; mt++){
        #pragma unroll
        for (int nt=0; nt<4; nt++){
            int colb = bn + warp_n*32 + nt*8 + c0l;
            #pragma unroll
            for (int h=0; h<2; h++){     // h=0: rows +0, h=1: rows +8 (d2,d3)
                int rowg = bm + warp_m*64 + mt*16 + r0l + h*8;
                float v0 = acc[mt][nt][2*h+0];
                float v1 = acc[mt][nt][2*h+1];
                if (EPI==0){
                    if (bias){ v0 += bias[colb]; v1 += bias[colb+1]; }
                    Yf[(size_t)rowg*N + colb]   = v0;
                    Yf[(size_t)rowg*N + colb+1] = v1;
                } else if (EPI==1){
                    v0 += bias[colb]; v1 += bias[colb+1];
                    __nv_bfloat16 hh,ll;
                    split_bf16(v0,hh,ll); Yh[(size_t)rowg*N+colb]=hh;   Yl[(size_t)rowg*N+colb]=ll;
                    split_bf16(v1,hh,ll); Yh[(size_t)rowg*N+colb+1]=hh; Yl[(size_t)rowg*N+colb+1]=ll;
                } else {
                    v0 += Dv[colb]  *hn[(size_t)rowg*DMOD + colb];
                    v1 += Dv[colb+1]*hn[(size_t)rowg*DMOD + colb+1];
                    v0 = gelu_f(v0); v1 = gelu_f(v1);
                    __nv_bfloat16 hh,ll;
                    split_bf16(v0,hh,ll); Yh[(size_t)rowg*N+colb]=hh;   Yl[(size_t)rowg*N+colb]=ll;
                    split_bf16(v1,hh,ll); Yh[(size_t)rowg*N+colb+1]=hh; Yl[(size_t)rowg*N+colb+1]=ll;
                }
            }
        }
    }
}

// ---------------- fp32 -> bf16 hi/lo conversion ------------------------------------
__global__ __launch_bounds__(256)
void conv_k(const float* __restrict__ src, __nv_bfloat16* __restrict__ dh,
            __nv_bfloat16* __restrict__ dl, int n, float scale)
{
    int i = blockIdx.x*256 + threadIdx.x;
    if (i >= n) return;
    float v = src[i]*scale;
    __nv_bfloat16 h,l; split_bf16(v,h,l);
    dh[i]=h; dl[i]=l;
}

// ---------------- LayerNorm: fp32 out + bf16 hi/lo out -----------------------------
__global__ __launch_bounds__(128)
void ln_k(const float* __restrict__ X, const float* __restrict__ g,
          const float* __restrict__ b, float* __restrict__ Y,
          __nv_bfloat16* __restrict__ Yh, __nv_bfloat16* __restrict__ Yl)
{
    int row = blockIdx.x;
    const float4* x4 = (const float4*)(X + (size_t)row*DMOD);
    float4 v = x4[threadIdx.x];
    float s  = v.x+v.y+v.z+v.w;
    float s2 = v.x*v.x+v.y*v.y+v.z*v.z+v.w*v.w;
    #pragma unroll
    for (int o=16;o>0;o>>=1){
        s  += __shfl_xor_sync(0xffffffffu, s , o);
        s2 += __shfl_xor_sync(0xffffffffu, s2, o);
    }
    __shared__ float ss[4], ss2[4];
    int w = threadIdx.x >> 5;
    if ((threadIdx.x & 31)==0){ ss[w]=s; ss2[w]=s2; }
    __syncthreads();
    s  = ss[0]+ss[1]+ss[2]+ss[3];
    s2 = ss2[0]+ss2[1]+ss2[2]+ss2[3];
    float mean = s * (1.0f/DMOD);
    float var  = s2 * (1.0f/DMOD) - mean*mean;
    float inv  = rsqrtf(var + 1e-5f);
    float4 gg = ((const float4*)g)[threadIdx.x];
    float4 bb = ((const float4*)b)[threadIdx.x];
    float o0 = (v.x-mean)*inv*gg.x + bb.x;
    float o1 = (v.y-mean)*inv*gg.y + bb.y;
    float o2 = (v.z-mean)*inv*gg.z + bb.z;
    float o3 = (v.w-mean)*inv*gg.w + bb.w;
    float4 of; of.x=o0; of.y=o1; of.z=o2; of.w=o3;
    ((float4*)(Y + (size_t)row*DMOD))[threadIdx.x] = of;
    size_t bo = (size_t)row*DMOD + threadIdx.x*4;
    __nv_bfloat16 h,l;
    split_bf16(o0,h,l); Yh[bo+0]=h; Yl[bo+0]=l;
    split_bf16(o1,h,l); Yh[bo+1]=h; Yl[bo+1]=l;
    split_bf16(o2,h,l); Yh[bo+2]=h; Yl[bo+2]=l;
    split_bf16(o3,h,l); Yh[bo+3]=h; Yl[bo+3]=l;
}

// ---------------- LinOSS IM scan (fp32 in, bf16 hi/lo out) -------------------------
__global__ __launch_bounds__(128)
void scan_k(const float* __restrict__ bur, const float* __restrict__ bui,
            __nv_bfloat16* __restrict__ xsrh, __nv_bfloat16* __restrict__ xsrl,
            __nv_bfloat16* __restrict__ xsih, __nv_bfloat16* __restrict__ xsil,
            const float* __restrict__ A_diag, const float* __restrict__ log_steps)
{
    int idx  = blockIdx.x*128 + threadIdx.x;   // 0..8191
    int n    = idx & 511;
    int b    = (idx >> 9) & 7;
    int part = idx >> 12;                      // 0 real, 1 imag

    float A   = fmaxf(A_diag[n], 0.0f);
    float dt  = sigmoid_f(log_steps[n]);
    float dtA = dt*dt*A;
    float S   = 1.0f/(1.0f+dtA);
    float m11 = 1.0f - dtA*S;
    float m12 = -dt*A*S;
    float m21 = dt*S;
    float m22 = S;
    float cz  = m11*dt;
    float cx  = m21*dt;

    const float* bu = (part ? bui : bur) + (size_t)b*LSEQ*DMOD + n;
    __nv_bfloat16* xh = (part ? xsih : xsrh) + (size_t)b*LSEQ*DMOD + n;
    __nv_bfloat16* xl = (part ? xsil : xsrl) + (size_t)b*LSEQ*DMOD + n;

    float z = 0.0f, x = 0.0f;
    for (int l0=0; l0<LSEQ; l0+=8){
        float v[8];
        #pragma unroll
        for (int u=0;u<8;u++) v[u] = __ldg(&bu[(size_t)(l0+u)*DMOD]);
        #pragma unroll
        for (int u=0;u<8;u++){
            float zn = fmaf(m11, z, fmaf(m12, x, cz*v[u]));
            float xn = fmaf(m21, z, fmaf(m22, x, cx*v[u]));
            z = zn; x = xn;
            __nv_bfloat16 h,l; split_bf16(x,h,l);
            xh[(size_t)(l0+u)*DMOD] = h;
            xl[(size_t)(l0+u)*DMOD] = l;
        }
    }
}

// ---------------- GLU + residual: r = skip + g1*sigmoid(g2) -> bf16 hi/lo ----------
__global__ __launch_bounds__(256)
void glu_res_k(const float* __restrict__ skip, const float* __restrict__ a,
               const float* __restrict__ bgate,
               __nv_bfloat16* __restrict__ rh, __nv_bfloat16* __restrict__ rl, int n4)
{
    int i = blockIdx.x*blockDim.x + threadIdx.x;
    if (i >= n4) return;
    float4 s  = ((const float4*)skip )[i];
    float4 av = ((const float4*)a    )[i];
    float4 gv = ((const float4*)bgate)[i];
    float o0 = s.x + av.x*sigmoid_f(gv.x);
    float o1 = s.y + av.y*sigmoid_f(gv.y);
    float o2 = s.z + av.z*sigmoid_f(gv.z);
    float o3 = s.w + av.w*sigmoid_f(gv.w);
    size_t bo = (size_t)i*4;
    __nv_bfloat16 h,l;
    split_bf16(o0,h,l); rh[bo+0]=h; rl[bo+0]=l;
    split_bf16(o1,h,l); rh[bo+1]=h; rl[bo+1]=l;
    split_bf16(o2,h,l); rh[bo+2]=h; rl[bo+2]=l;
    split_bf16(o3,h,l); rh[bo+3]=h; rl[bo+3]=l;
}

// ---------------- host launcher ----------------------------------------------------
static float* symf(const void* s){ void* p=nullptr; cudaGetSymbolAddress(&p, s); return (float*)p; }
static __nv_bfloat16* symb(const void* s){ void* p=nullptr; cudaGetSymbolAddress(&p, s); return (__nv_bfloat16*)p; }

extern "C" void kernel_launch(void* const* d_in, const int* in_sizes, int n_in,
                              void* d_out, int out_size)
{
    const float* x      = (const float*)d_in[0];
    const float* W_in   = (const float*)d_in[1];
    const float* b_in   = (const float*)d_in[2];
    const float* W_enc  = (const float*)d_in[3];
    const float* b_enc  = (const float*)d_in[4];
    const float* ln_g   = (const float*)d_in[5];
    const float* ln_b   = (const float*)d_in[6];
    const float* A_diag = (const float*)d_in[7];
    const float* log_st = (const float*)d_in[8];
    const float* B_re   = (const float*)d_in[9];
    const float* B_im   = (const float*)d_in[10];
    const float* C_re   = (const float*)d_in[11];
    const float* C_im   = (const float*)d_in[12];
    const float* Dvec   = (const float*)d_in[13];
    const float* glu_w1 = (const float*)d_in[14];
    const float* glu_b1 = (const float*)d_in[15];
    const float* glu_w2 = (const float*)d_in[16];
    const float* glu_b2 = (const float*)d_in[17];
    const float* W_dec  = (const float*)d_in[18];
    const float* b_dec  = (const float*)d_in[19];
    const float* W_out  = (const float*)d_in[20];
    const float* b_out  = (const float*)d_in[21];
    float* out = (float*)d_out;

    float* skip = symf(g_skip); float* hn = symf(g_hn);
    float* bur = symf(g_bur);   float* bui = symf(g_bui);
    float* gg1 = symf(g_g1);    float* gg2 = symf(g_g2);

    __nv_bfloat16 *xh=symb(g_xh), *xl=symb(g_xl);
    __nv_bfloat16 *h1h=symb(g_h1h), *h1l=symb(g_h1l);
    __nv_bfloat16 *hnh=symb(g_hnh), *hnl=symb(g_hnl);
    __nv_bfloat16 *xsrh=symb(g_xsrh), *xsrl=symb(g_xsrl);
    __nv_bfloat16 *xsih=symb(g_xsih), *xsil=symb(g_xsil);
    __nv_bfloat16 *yh=symb(g_yh), *yl=symb(g_yl);
    __nv_bfloat16 *rh=symb(g_rh), *rl=symb(g_rl);
    __nv_bfloat16 *hdh=symb(g_hdh), *hdl=symb(g_hdl);
    __nv_bfloat16 *Winh=symb(g_Winh), *Winl=symb(g_Winl);
    __nv_bfloat16 *Wench=symb(g_Wench), *Wencl=symb(g_Wencl);
    __nv_bfloat16 *Breh=symb(g_Breh), *Brel=symb(g_Brel);
    __nv_bfloat16 *Bimh=symb(g_Bimh), *Biml=symb(g_Biml);
    __nv_bfloat16 *Creh=symb(g_Creh), *Crel=symb(g_Crel);
    __nv_bfloat16 *Cimh=symb(g_Cimh), *Ciml=symb(g_Ciml);
    __nv_bfloat16 *W1h=symb(g_W1h), *W1l=symb(g_W1l);
    __nv_bfloat16 *W2h=symb(g_W2h), *W2l=symb(g_W2l);
    __nv_bfloat16 *Wdech=symb(g_Wdech), *Wdecl=symb(g_Wdecl);
    __nv_bfloat16 *Wouth=symb(g_Wouth), *Woutl=symb(g_Woutl);

    cudaFuncSetAttribute(mma_gemm<0>, cudaFuncAttributeMaxDynamicSharedMemorySize, GSMEM_TOTAL);
    cudaFuncSetAttribute(mma_gemm<1>, cudaFuncAttributeMaxDynamicSharedMemorySize, GSMEM_TOTAL);
    cudaFuncSetAttribute(mma_gemm<2>, cudaFuncAttributeMaxDynamicSharedMemorySize, GSMEM_TOTAL);

    // ---- conversions ----
    const int DD = DMOD*DMOD, DH = DMOD*HIN;
    conv_k<<<(MTOT*HIN+255)/256,256>>>(x, xh, xl, MTOT*HIN, 1.0f);
    conv_k<<<(DH+255)/256,256>>>(W_in,  Winh,  Winl,  DH, 1.0f);
    conv_k<<<(DD+255)/256,256>>>(W_enc, Wench, Wencl, DD, 1.0f);
    conv_k<<<(DD+255)/256,256>>>(B_re,  Breh,  Brel,  DD, 1.0f);
    conv_k<<<(DD+255)/256,256>>>(B_im,  Bimh,  Biml,  DD, 1.0f);
    conv_k<<<(DD+255)/256,256>>>(C_re,  Creh,  Crel,  DD, 1.0f);
    conv_k<<<(DD+255)/256,256>>>(C_im,  Cimh,  Ciml,  DD, -1.0f);   // pre-negated
    conv_k<<<(DD+255)/256,256>>>(glu_w1, W1h, W1l, DD, 1.0f);
    conv_k<<<(DD+255)/256,256>>>(glu_w2, W2h, W2l, DD, 1.0f);
    conv_k<<<(DD+255)/256,256>>>(W_dec, Wdech, Wdecl, DD, 1.0f);
    conv_k<<<(DH+255)/256,256>>>(W_out, Wouth, Woutl, DH, 1.0f);

    dim3 gD(DMOD/128, MTOT/128);   // (4,128)
    dim3 gO(HIN/128,  MTOT/128);   // (1,128)

    // 1) h1 = x @ W_in^T + b_in  -> bf16 pair
    mma_gemm<1><<<gD,256,GSMEM_TOTAL>>>(xh,xl,Winh,Winl, nullptr,nullptr,nullptr,nullptr,
                                        b_in,nullptr,nullptr, nullptr,h1h,h1l, DMOD,HIN,3);
    // 2) skip = h1 @ W_enc^T + b_enc  -> fp32
    mma_gemm<0><<<gD,256,GSMEM_TOTAL>>>(h1h,h1l,Wench,Wencl, nullptr,nullptr,nullptr,nullptr,
                                        b_enc,nullptr,nullptr, skip,nullptr,nullptr, DMOD,DMOD,3);
    // 3) hn = LN(skip)  (fp32 + bf16 pair)
    ln_k<<<MTOT,128>>>(skip, ln_g, ln_b, hn, hnh, hnl);
    // 4) Bu = hn @ B^T (re, im)  -> fp32
    mma_gemm<0><<<gD,256,GSMEM_TOTAL>>>(hnh,hnl,Breh,Brel, nullptr,nullptr,nullptr,nullptr,
                                        nullptr,nullptr,nullptr, bur,nullptr,nullptr, DMOD,DMOD,3);
    mma_gemm<0><<<gD,256,GSMEM_TOTAL>>>(hnh,hnl,Bimh,Biml, nullptr,nullptr,nullptr,nullptr,
                                        nullptr,nullptr,nullptr, bui,nullptr,nullptr, DMOD,DMOD,3);
    // 5) scan -> xs (bf16 pairs)
    scan_k<<<64,128>>>(bur, bui, xsrh, xsrl, xsih, xsil, A_diag, log_st);
    // 6) y = gelu(xsr@C_re^T - xsi@C_im^T + D*hn)  -> bf16 pair (dual operand, 6 passes)
    mma_gemm<2><<<gD,256,GSMEM_TOTAL>>>(xsrh,xsrl,Creh,Crel, xsih,xsil,Cimh,Ciml,
                                        nullptr,Dvec,hn, nullptr,yh,yl, DMOD,DMOD,6);
    // 7) GLU branches -> fp32
    mma_gemm<0><<<gD,256,GSMEM_TOTAL>>>(yh,yl,W1h,W1l, nullptr,nullptr,nullptr,nullptr,
                                        glu_b1,nullptr,nullptr, gg1,nullptr,nullptr, DMOD,DMOD,3);
    mma_gemm<0><<<gD,256,GSMEM_TOTAL>>>(yh,yl,W2h,W2l, nullptr,nullptr,nullptr,nullptr,
                                        glu_b2,nullptr,nullptr, gg2,nullptr,nullptr, DMOD,DMOD,3);
    // 8) r = skip + gg1*sigmoid(gg2) -> bf16 pair
    int n4 = MTOT*DMOD/4;
    glu_res_k<<<(n4+255)/256,256>>>(skip, gg1, gg2, rh, rl, n4);
    // 9) hd = r @ W_dec^T + b_dec -> bf16 pair
    mma_gemm<1><<<gD,256,GSMEM_TOTAL>>>(rh,rl,Wdech,Wdecl, nullptr,nullptr,nullptr,nullptr,
                                        b_dec,nullptr,nullptr, nullptr,hdh,hdl, DMOD,DMOD,3);
    // 10) out = hd @ W_out^T + b_out -> fp32 (N=128)
    mma_gemm<0><<<gO,256,GSMEM_TOTAL>>>(hdh,hdl,Wouth,Woutl, nullptr,nullptr,nullptr,nullptr,
                                        b_out,nullptr,nullptr, out,nullptr,nullptr, HIN,DMOD,3);
}

// round 11
// speedup vs baseline: 2.5876x; 1.5271x over previous
#include <cuda_runtime.h>
#include <cuda_bf16.h>
#include <math.h>
#include <stdint.h>

#define MTOT 16384   // B*L
#define DMOD 512
#define HIN  128
#define LSEQ 2048

typedef __nv_bfloat16 bf16;

// ---------------- scratch (static device globals: allocation-free) ----------------
__device__ float g_skip[MTOT*DMOD];
__device__ float g_hn  [MTOT*DMOD];
__device__ float g_bu  [MTOT*1024];     // [.,0:512)=Bu_re  [.,512:1024)=Bu_im
__device__ float g_gg  [MTOT*1024];     // [.,0:512)=g1     [.,512:1024)=g2
__device__ float g_bglu[1024];          // concat glu_b1 || glu_b2

__device__ bf16 g_xh [MTOT*HIN],  g_xl [MTOT*HIN];
__device__ bf16 g_h1h[MTOT*DMOD], g_h1l[MTOT*DMOD];
__device__ bf16 g_hnh[MTOT*DMOD], g_hnl[MTOT*DMOD];
__device__ bf16 g_xsrh[MTOT*DMOD], g_xsrl[MTOT*DMOD];
__device__ bf16 g_xsih[MTOT*DMOD], g_xsil[MTOT*DMOD];
__device__ bf16 g_yh [MTOT*DMOD], g_yl [MTOT*DMOD];
__device__ bf16 g_rh [MTOT*DMOD], g_rl [MTOT*DMOD];
__device__ bf16 g_hdh[MTOT*DMOD], g_hdl[MTOT*DMOD];

// weight hi/lo pairs
__device__ bf16 g_Winh [DMOD*HIN],   g_Winl [DMOD*HIN];
__device__ bf16 g_Wench[DMOD*DMOD],  g_Wencl[DMOD*DMOD];
__device__ bf16 g_Bcath[1024*DMOD],  g_Bcatl[1024*DMOD];   // B_re rows 0-511, B_im rows 512-1023
__device__ bf16 g_Creh [DMOD*DMOD],  g_Crel [DMOD*DMOD];
__device__ bf16 g_Cimh [DMOD*DMOD],  g_Ciml [DMOD*DMOD];   // pre-negated
__device__ bf16 g_Wgh  [1024*DMOD],  g_Wgl  [1024*DMOD];   // glu_w1 rows 0-511, glu_w2 rows 512-1023
__device__ bf16 g_Wdech[DMOD*DMOD],  g_Wdecl[DMOD*DMOD];
__device__ bf16 g_Wouth[HIN*DMOD],   g_Woutl[HIN*DMOD];

__device__ __forceinline__ float gelu_f(float x){
    float x3 = x*x*x;
    float t = tanhf(0.7978845608028654f*(x + 0.044715f*x3));
    return 0.5f*x*(1.0f+t);
}
__device__ __forceinline__ float sigmoid_f(float x){ return 1.0f/(1.0f+expf(-x)); }
__device__ __forceinline__ void split_bf16(float v, bf16& h, bf16& l){
    h = __float2bfloat16(v);
    l = __float2bfloat16(v - __bfloat162float(h));
}
__device__ __forceinline__ uint32_t smem_u32(const void* p){
    uint32_t a;
    asm("{ .reg .u64 t; cvta.to.shared.u64 t, %1; cvt.u32.u64 %0, t; }" : "=r"(a) : "l"(p));
    return a;
}
__device__ __forceinline__ void cpa16(uint32_t dst, const void* src){
    asm volatile("cp.async.cg.shared.global [%0], [%1], 16;" :: "r"(dst), "l"(src));
}
__device__ __forceinline__ void cpa_commit(){ asm volatile("cp.async.commit_group;" ::: "memory"); }
__device__ __forceinline__ void ldm4(uint32_t addr, uint32_t& r0, uint32_t& r1,
                                     uint32_t& r2, uint32_t& r3){
    asm volatile("ldmatrix.sync.aligned.m8n8.x4.shared.b16 {%0,%1,%2,%3}, [%4];"
                 : "=r"(r0), "=r"(r1), "=r"(r2), "=r"(r3) : "r"(addr));
}
__device__ __forceinline__ void mma16816(float* d, const uint32_t* a,
                                         uint32_t b0, uint32_t b1){
    asm volatile("mma.sync.aligned.m16n8k16.row.col.f32.bf16.bf16.f32 "
                 "{%0,%1,%2,%3}, {%4,%5,%6,%7}, {%8,%9}, {%0,%1,%2,%3};"
                 : "+f"(d[0]), "+f"(d[1]), "+f"(d[2]), "+f"(d[3])
                 : "r"(a[0]), "r"(a[1]), "r"(a[2]), "r"(a[3]), "r"(b0), "r"(b1));
}

// ---------------- mma.sync GEMM with shared hi/lo tiles ----------------------------
// Per K-chunk (32): load Ah,Al,Bh,Bl once; accumulate Ah@Bh + Ah@Bl + Al@Bh.
// npair=2 repeats with second operand set (for the complex C GEMM).
// EPI 0: fp32 out (+bias). EPI 1: bf16 hi/lo (+bias). EPI 2: gelu(acc+Dv*hn) -> hi/lo.
#define RS    80
#define TILEB (128*RS)              // 10240 per tile
#define STG   (4*TILEB)             // 40960 per stage (Ah,Al,Bh,Bl)
#define NSTG  2
#define GSMEM_TOTAL (NSTG*STG)      // 81920

template<int EPI>
__global__ __launch_bounds__(256,2)
void mma_gemm(const bf16* __restrict__ a1h, const bf16* __restrict__ a1l,
              const bf16* __restrict__ b1h, const bf16* __restrict__ b1l,
              const bf16* __restrict__ a2h, const bf16* __restrict__ a2l,
              const bf16* __restrict__ b2h, const bf16* __restrict__ b2l,
              const float* __restrict__ bias, const float* __restrict__ Dv,
              const float* __restrict__ hn,
              float* __restrict__ Yf, bf16* __restrict__ Yh, bf16* __restrict__ Yl,
              int N, int K, int npair)
{
    extern __shared__ __align__(128) char smem[];
    uint32_t sb = smem_u32(smem);
    const int tid = threadIdx.x, wid = tid>>5, lane = tid&31;
    const int warp_m = wid & 1, warp_n = wid >> 1;
    const int bm = blockIdx.y*128, bn = blockIdx.x*128;

    const bf16* AH[2] = {a1h, a2h};  const bf16* AL[2] = {a1l, a2l};
    const bf16* BH[2] = {b1h, b2h};  const bf16* BL[2] = {b1l, b2l};

    const int kcp = K >> 5;
    const int nch = npair * kcp;

    const int row = tid >> 1;
    const int cp2 = (tid & 1)*2;

    float acc[4][4][4];
    #pragma unroll
    for (int i=0;i<4;i++)
        #pragma unroll
        for (int j=0;j<4;j++){ acc[i][j][0]=0.f; acc[i][j][1]=0.f; acc[i][j][2]=0.f; acc[i][j][3]=0.f; }

    // chunk loader: 4 tiles (Ah, Al, Bh, Bl), 8 cp.async per thread
    auto load_chunk = [&](int t){
        int pr = t / kcp, kc = t - pr*kcp;
        uint32_t base = sb + (t & 1)*STG + row*RS + cp2*16;
        const bf16* s0 = AH[pr] + (size_t)(bm+row)*K + kc*32 + cp2*8;
        const bf16* s1 = AL[pr] + (size_t)(bm+row)*K + kc*32 + cp2*8;
        const bf16* s2 = BH[pr] + (size_t)(bn+row)*K + kc*32 + cp2*8;
        const bf16* s3 = BL[pr] + (size_t)(bn+row)*K + kc*32 + cp2*8;
        cpa16(base,            s0); cpa16(base+16,            s0+8);
        cpa16(base+  TILEB,    s1); cpa16(base+  TILEB+16,    s1+8);
        cpa16(base+2*TILEB,    s2); cpa16(base+2*TILEB+16,    s2+8);
        cpa16(base+3*TILEB,    s3); cpa16(base+3*TILEB+16,    s3+8);
    };

    load_chunk(0);
    cpa_commit();

    const int lrow = (lane & 7) + ((lane >> 3) & 1)*8;
    const int lcol = (lane >> 4)*16;

    for (int t=0; t<nch; t++){
        if (t+1 < nch){
            load_chunk(t+1);
            cpa_commit();
            asm volatile("cp.async.wait_group 1;" ::: "memory");
        } else {
            asm volatile("cp.async.wait_group 0;" ::: "memory");
        }
        __syncthreads();

        uint32_t ahb = sb + (t&1)*STG;
        uint32_t alb = ahb +   TILEB;
        uint32_t bhb = ahb + 2*TILEB;
        uint32_t blb = ahb + 3*TILEB;

        #pragma unroll
        for (int ks=0; ks<2; ks++){
            uint32_t koff = ks*32 + lcol;
            uint32_t ah[4][4], bh[2][4], bl[2][4];
            #pragma unroll
            for (int mt=0; mt<4; mt++)
                ldm4(ahb + (uint32_t)(warp_m*64 + mt*16 + lrow)*RS + koff,
                     ah[mt][0], ah[mt][1], ah[mt][2], ah[mt][3]);
            #pragma unroll
            for (int g=0; g<2; g++){
                ldm4(bhb + (uint32_t)(warp_n*32 + g*16 + lrow)*RS + koff,
                     bh[g][0], bh[g][1], bh[g][2], bh[g][3]);
                ldm4(blb + (uint32_t)(warp_n*32 + g*16 + lrow)*RS + koff,
                     bl[g][0], bl[g][1], bl[g][2], bl[g][3]);
            }
            // Ah@Bh and Ah@Bl
            #pragma unroll
            for (int mt=0; mt<4; mt++)
                #pragma unroll
                for (int nt=0; nt<4; nt++){
                    int g = nt >> 1, sub = nt & 1;
                    mma16816(acc[mt][nt], ah[mt], bh[g][sub], bh[g][sub+2]);
                    mma16816(acc[mt][nt], ah[mt], bl[g][sub], bl[g][sub+2]);
                }
            // Al@Bh (load al after bl is dead to cap register pressure)
            uint32_t al[4][4];
            #pragma unroll
            for (int mt=0; mt<4; mt++)
                ldm4(alb + (uint32_t)(warp_m*64 + mt*16 + lrow)*RS + koff,
                     al[mt][0], al[mt][1], al[mt][2], al[mt][3]);
            #pragma unroll
            for (int mt=0; mt<4; mt++)
                #pragma unroll
                for (int nt=0; nt<4; nt++){
                    int g = nt >> 1, sub = nt & 1;
                    mma16816(acc[mt][nt], al[mt], bh[g][sub], bh[g][sub+2]);
                }
        }
        __syncthreads();
    }

    // ---------------- epilogue ----------------
    const int r0l = lane >> 2;
    const int c0l = (lane & 3)*2;
    #pragma unroll
    for (int mt=0; mt<4; mt++){
        #pragma unroll
        for (int nt=0; nt<4; nt++){
            int colb = bn + warp_n*32 + nt*8 + c0l;
            #pragma unroll
            for (int h=0; h<2; h++){
                int rowg = bm + warp_m*64 + mt*16 + r0l + h*8;
                float v0 = acc[mt][nt][2*h+0];
                float v1 = acc[mt][nt][2*h+1];
                if (EPI==0){
                    if (bias){ v0 += bias[colb]; v1 += bias[colb+1]; }
                    Yf[(size_t)rowg*N + colb]   = v0;
                    Yf[(size_t)rowg*N + colb+1] = v1;
                } else if (EPI==1){
                    v0 += bias[colb]; v1 += bias[colb+1];
                    bf16 hh,ll;
                    split_bf16(v0,hh,ll); Yh[(size_t)rowg*N+colb]=hh;   Yl[(size_t)rowg*N+colb]=ll;
                    split_bf16(v1,hh,ll); Yh[(size_t)rowg*N+colb+1]=hh; Yl[(size_t)rowg*N+colb+1]=ll;
                } else {
                    v0 += Dv[colb]  *hn[(size_t)rowg*DMOD + colb];
                    v1 += Dv[colb+1]*hn[(size_t)rowg*DMOD + colb+1];
                    v0 = gelu_f(v0); v1 = gelu_f(v1);
                    bf16 hh,ll;
                    split_bf16(v0,hh,ll); Yh[(size_t)rowg*N+colb]=hh;   Yl[(size_t)rowg*N+colb]=ll;
                    split_bf16(v1,hh,ll); Yh[(size_t)rowg*N+colb+1]=hh; Yl[(size_t)rowg*N+colb+1]=ll;
                }
            }
        }
    }
}

// ---------------- batched fp32 -> bf16 hi/lo conversion (ALL inputs, 1 launch) -----
#define SZ_X   (MTOT*HIN)    // 2097152
#define SZ_DH  (DMOD*HIN)    // 65536
#define SZ_DD  (DMOD*DMOD)   // 262144
__global__ __launch_bounds__(256)
void conv_all(const float* __restrict__ x,    const float* __restrict__ W_in,
              const float* __restrict__ W_enc,const float* __restrict__ B_re,
              const float* __restrict__ B_im, const float* __restrict__ C_re,
              const float* __restrict__ C_im, const float* __restrict__ w1,
              const float* __restrict__ w2,   const float* __restrict__ W_dec,
              const float* __restrict__ W_out,const float* __restrict__ gb1,
              const float* __restrict__ gb2)
{
    const int O0 = SZ_X;                 // x
    const int O1 = O0 + SZ_DH;           // W_in
    const int O2 = O1 + SZ_DD;           // W_enc
    const int O3 = O2 + SZ_DD;           // B_re
    const int O4 = O3 + SZ_DD;           // B_im
    const int O5 = O4 + SZ_DD;           // C_re
    const int O6 = O5 + SZ_DD;           // C_im (negated)
    const int O7 = O6 + SZ_DD;           // w1
    const int O8 = O7 + SZ_DD;           // w2
    const int O9 = O8 + SZ_DD;           // W_dec
    const int O10= O9 + SZ_DH;           // W_out
    const int TOT= O10 + 1024;           // bias concat

    int i = blockIdx.x*256 + threadIdx.x;
    if (i >= TOT) return;
    if (i >= O10){                       // GLU bias concat (fp32 copy)
        int k = i - O10;
        g_bglu[k] = (k < 512) ? gb1[k] : gb2[k-512];
        return;
    }
    const float* src; bf16 *dh, *dl; int off; float sc = 1.0f;
    if      (i < O0){ src=x;     dh=g_xh;    dl=g_xl;    off=i;    }
    else if (i < O1){ src=W_in;  dh=g_Winh;  dl=g_Winl;  off=i-O0; }
    else if (i < O2){ src=W_enc; dh=g_Wench; dl=g_Wencl; off=i-O1; }
    else if (i < O3){ src=B_re;  dh=g_Bcath; dl=g_Bcatl; off=i-O2; }
    else if (i < O4){ src=B_im;  dh=g_Bcath+SZ_DD; dl=g_Bcatl+SZ_DD; off=i-O3; }
    else if (i < O5){ src=C_re;  dh=g_Creh;  dl=g_Crel;  off=i-O4; }
    else if (i < O6){ src=C_im;  dh=g_Cimh;  dl=g_Ciml;  off=i-O5; sc=-1.0f; }
    else if (i < O7){ src=w1;    dh=g_Wgh;   dl=g_Wgl;   off=i-O6; }
    else if (i < O8){ src=w2;    dh=g_Wgh+SZ_DD; dl=g_Wgl+SZ_DD; off=i-O7; }
    else if (i < O9){ src=W_dec; dh=g_Wdech; dl=g_Wdecl; off=i-O8; }
    else            { src=W_out; dh=g_Wouth; dl=g_Woutl; off=i-O9; }
    float v = src[off]*sc;
    bf16 h,l; split_bf16(v,h,l);
    dh[off]=h; dl[off]=l;
}

// ---------------- LayerNorm: fp32 out + bf16 hi/lo out -----------------------------
__global__ __launch_bounds__(128)
void ln_k(const float* __restrict__ X, const float* __restrict__ g,
          const float* __restrict__ b, float* __restrict__ Y,
          bf16* __restrict__ Yh, bf16* __restrict__ Yl)
{
    int row = blockIdx.x;
    const float4* x4 = (const float4*)(X + (size_t)row*DMOD);
    float4 v = x4[threadIdx.x];
    float s  = v.x+v.y+v.z+v.w;
    float s2 = v.x*v.x+v.y*v.y+v.z*v.z+v.w*v.w;
    #pragma unroll
    for (int o=16;o>0;o>>=1){
        s  += __shfl_xor_sync(0xffffffffu, s , o);
        s2 += __shfl_xor_sync(0xffffffffu, s2, o);
    }
    __shared__ float ss[4], ss2[4];
    int w = threadIdx.x >> 5;
    if ((threadIdx.x & 31)==0){ ss[w]=s; ss2[w]=s2; }
    __syncthreads();
    s  = ss[0]+ss[1]+ss[2]+ss[3];
    s2 = ss2[0]+ss2[1]+ss2[2]+ss2[3];
    float mean = s * (1.0f/DMOD);
    float var  = s2 * (1.0f/DMOD) - mean*mean;
    float inv  = rsqrtf(var + 1e-5f);
    float4 gg = ((const float4*)g)[threadIdx.x];
    float4 bb = ((const float4*)b)[threadIdx.x];
    float o0 = (v.x-mean)*inv*gg.x + bb.x;
    float o1 = (v.y-mean)*inv*gg.y + bb.y;
    float o2 = (v.z-mean)*inv*gg.z + bb.z;
    float o3 = (v.w-mean)*inv*gg.w + bb.w;
    float4 of; of.x=o0; of.y=o1; of.z=o2; of.w=o3;
    ((float4*)(Y + (size_t)row*DMOD))[threadIdx.x] = of;
    size_t bo = (size_t)row*DMOD + threadIdx.x*4;
    bf16 h,l;
    split_bf16(o0,h,l); Yh[bo+0]=h; Yl[bo+0]=l;
    split_bf16(o1,h,l); Yh[bo+1]=h; Yl[bo+1]=l;
    split_bf16(o2,h,l); Yh[bo+2]=h; Yl[bo+2]=l;
    split_bf16(o3,h,l); Yh[bo+3]=h; Yl[bo+3]=l;
}

// ---------------- LinOSS IM scan (reads fused g_bu layout, stride 1024) ------------
__global__ __launch_bounds__(128)
void scan_k(const float* __restrict__ bu,
            bf16* __restrict__ xsrh, bf16* __restrict__ xsrl,
            bf16* __restrict__ xsih, bf16* __restrict__ xsil,
            const float* __restrict__ A_diag, const float* __restrict__ log_steps)
{
    int idx  = blockIdx.x*128 + threadIdx.x;   // 0..8191
    int n    = idx & 511;
    int b    = (idx >> 9) & 7;
    int part = idx >> 12;                      // 0 real, 1 imag

    float A   = fmaxf(A_diag[n], 0.0f);
    float dt  = sigmoid_f(log_steps[n]);
    float dtA = dt*dt*A;
    float S   = 1.0f/(1.0f+dtA);
    float m11 = 1.0f - dtA*S;
    float m12 = -dt*A*S;
    float m21 = dt*S;
    float m22 = S;
    float cz  = m11*dt;
    float cx  = m21*dt;

    const float* src = bu + (size_t)b*LSEQ*1024 + part*512 + n;
    bf16* xh = (part ? xsih : xsrh) + (size_t)b*LSEQ*DMOD + n;
    bf16* xl = (part ? xsil : xsrl) + (size_t)b*LSEQ*DMOD + n;

    float z = 0.0f, x = 0.0f;
    for (int l0=0; l0<LSEQ; l0+=8){
        float v[8];
        #pragma unroll
        for (int u=0;u<8;u++) v[u] = __ldg(&src[(size_t)(l0+u)*1024]);
        #pragma unroll
        for (int u=0;u<8;u++){
            float zn = fmaf(m11, z, fmaf(m12, x, cz*v[u]));
            float xn = fmaf(m21, z, fmaf(m22, x, cx*v[u]));
            z = zn; x = xn;
            bf16 h,l; split_bf16(x,h,l);
            xh[(size_t)(l0+u)*DMOD] = h;
            xl[(size_t)(l0+u)*DMOD] = l;
        }
    }
}

// ---------------- GLU + residual (reads fused g_gg layout) -------------------------
__global__ __launch_bounds__(256)
void glu_res_k(const float* __restrict__ skip, const float* __restrict__ gg,
               bf16* __restrict__ rh, bf16* __restrict__ rl, int n4)
{
    int i = blockIdx.x*blockDim.x + threadIdx.x;
    if (i >= n4) return;
    int row  = (i*4) >> 9;          // /512
    int col4 = (i*4) & 511;
    float4 s  = *(const float4*)(skip + (size_t)row*512  + col4);
    float4 av = *(const float4*)(gg   + (size_t)row*1024 + col4);
    float4 gv = *(const float4*)(gg   + (size_t)row*1024 + 512 + col4);
    float o0 = s.x + av.x*sigmoid_f(gv.x);
    float o1 = s.y + av.y*sigmoid_f(gv.y);
    float o2 = s.z + av.z*sigmoid_f(gv.z);
    float o3 = s.w + av.w*sigmoid_f(gv.w);
    size_t bo = (size_t)row*512 + col4;
    bf16 h,l;
    split_bf16(o0,h,l); rh[bo+0]=h; rl[bo+0]=l;
    split_bf16(o1,h,l); rh[bo+1]=h; rl[bo+1]=l;
    split_bf16(o2,h,l); rh[bo+2]=h; rl[bo+2]=l;
    split_bf16(o3,h,l); rh[bo+3]=h; rl[bo+3]=l;
}

// ---------------- host launcher ----------------------------------------------------
static float* symf(const void* s){ void* p=nullptr; cudaGetSymbolAddress(&p, s); return (float*)p; }
static bf16*  symb(const void* s){ void* p=nullptr; cudaGetSymbolAddress(&p, s); return (bf16*)p; }

extern "C" void kernel_launch(void* const* d_in, const int* in_sizes, int n_in,
                              void* d_out, int out_size)
{
    const float* x      = (const float*)d_in[0];
    const float* W_in   = (const float*)d_in[1];
    const float* b_in   = (const float*)d_in[2];
    const float* W_enc  = (const float*)d_in[3];
    const float* b_enc  = (const float*)d_in[4];
    const float* ln_g   = (const float*)d_in[5];
    const float* ln_b   = (const float*)d_in[6];
    const float* A_diag = (const float*)d_in[7];
    const float* log_st = (const float*)d_in[8];
    const float* B_re   = (const float*)d_in[9];
    const float* B_im   = (const float*)d_in[10];
    const float* C_re   = (const float*)d_in[11];
    const float* C_im   = (const float*)d_in[12];
    const float* Dvec   = (const float*)d_in[13];
    const float* glu_w1 = (const float*)d_in[14];
    const float* glu_b1 = (const float*)d_in[15];
    const float* glu_w2 = (const float*)d_in[16];
    const float* glu_b2 = (const float*)d_in[17];
    const float* W_dec  = (const float*)d_in[18];
    const float* b_dec  = (const float*)d_in[19];
    const float* W_out  = (const float*)d_in[20];
    const float* b_out  = (const float*)d_in[21];
    float* out = (float*)d_out;

    float* skip = symf(g_skip); float* hn = symf(g_hn);
    float* bu   = symf(g_bu);   float* gg = symf(g_gg);
    float* bglu = symf(g_bglu);

    bf16 *xh=symb(g_xh), *xl=symb(g_xl);
    bf16 *h1h=symb(g_h1h), *h1l=symb(g_h1l);
    bf16 *hnh=symb(g_hnh), *hnl=symb(g_hnl);
    bf16 *xsrh=symb(g_xsrh), *xsrl=symb(g_xsrl);
    bf16 *xsih=symb(g_xsih), *xsil=symb(g_xsil);
    bf16 *yh=symb(g_yh), *yl=symb(g_yl);
    bf16 *rh=symb(g_rh), *rl=symb(g_rl);
    bf16 *hdh=symb(g_hdh), *hdl=symb(g_hdl);
    bf16 *Winh=symb(g_Winh), *Winl=symb(g_Winl);
    bf16 *Wench=symb(g_Wench), *Wencl=symb(g_Wencl);
    bf16 *Bcath=symb(g_Bcath), *Bcatl=symb(g_Bcatl);
    bf16 *Creh=symb(g_Creh), *Crel=symb(g_Crel);
    bf16 *Cimh=symb(g_Cimh), *Ciml=symb(g_Ciml);
    bf16 *Wgh=symb(g_Wgh), *Wgl=symb(g_Wgl);
    bf16 *Wdech=symb(g_Wdech), *Wdecl=symb(g_Wdecl);
    bf16 *Wouth=symb(g_Wouth), *Woutl=symb(g_Woutl);

    cudaFuncSetAttribute(mma_gemm<0>, cudaFuncAttributeMaxDynamicSharedMemorySize, GSMEM_TOTAL);
    cudaFuncSetAttribute(mma_gemm<1>, cudaFuncAttributeMaxDynamicSharedMemorySize, GSMEM_TOTAL);
    cudaFuncSetAttribute(mma_gemm<2>, cudaFuncAttributeMaxDynamicSharedMemorySize, GSMEM_TOTAL);

    // 1) all conversions, one launch
    const int TOT_CONV = SZ_X + 2*SZ_DH + 8*SZ_DD + 1024;
    conv_all<<<(TOT_CONV+255)/256,256>>>(x, W_in, W_enc, B_re, B_im, C_re, C_im,
                                         glu_w1, glu_w2, W_dec, W_out, glu_b1, glu_b2);

    dim3 gD (DMOD/128, MTOT/128);   // (4,128)
    dim3 gD2(1024/128, MTOT/128);   // (8,128) fused dual-weight
    dim3 gO (HIN /128, MTOT/128);   // (1,128)

    // 2) h1 = x @ W_in^T + b_in  -> bf16 pair   (K=128)
    mma_gemm<1><<<gD,256,GSMEM_TOTAL>>>(xh,xl,Winh,Winl, nullptr,nullptr,nullptr,nullptr,
                                        b_in,nullptr,nullptr, nullptr,h1h,h1l, DMOD,HIN,1);
    // 3) skip = h1 @ W_enc^T + b_enc -> fp32
    mma_gemm<0><<<gD,256,GSMEM_TOTAL>>>(h1h,h1l,Wench,Wencl, nullptr,nullptr,nullptr,nullptr,
                                        b_enc,nullptr,nullptr, skip,nullptr,nullptr, DMOD,DMOD,1);
    // 4) hn = LN(skip)
    ln_k<<<MTOT,128>>>(skip, ln_g, ln_b, hn, hnh, hnl);
    // 5) bu = hn @ [B_re;B_im]^T  -> fp32, N=1024 (fused re+im)
    mma_gemm<0><<<gD2,256,GSMEM_TOTAL>>>(hnh,hnl,Bcath,Bcatl, nullptr,nullptr,nullptr,nullptr,
                                         nullptr,nullptr,nullptr, bu,nullptr,nullptr, 1024,DMOD,1);
    // 6) scan -> xs (bf16 pairs)
    scan_k<<<64,128>>>(bu, xsrh, xsrl, xsih, xsil, A_diag, log_st);
    // 7) y = gelu(xsr@C_re^T - xsi@C_im^T + D*hn) -> bf16 pair (npair=2)
    mma_gemm<2><<<gD,256,GSMEM_TOTAL>>>(xsrh,xsrl,Creh,Crel, xsih,xsil,Cimh,Ciml,
                                        nullptr,Dvec,hn, nullptr,yh,yl, DMOD,DMOD,2);
    // 8) gg = y @ [w1;w2]^T + [b1;b2] -> fp32, N=1024 (fused GLU branches)
    mma_gemm<0><<<gD2,256,GSMEM_TOTAL>>>(yh,yl,Wgh,Wgl, nullptr,nullptr,nullptr,nullptr,
                                         bglu,nullptr,nullptr, gg,nullptr,nullptr, 1024,DMOD,1);
    // 9) r = skip + g1*sigmoid(g2) -> bf16 pair
    int n4 = MTOT*DMOD/4;
    glu_res_k<<<(n4+255)/256,256>>>(skip, gg, rh, rl, n4);
    // 10) hd = r @ W_dec^T + b_dec -> bf16 pair
    mma_gemm<1><<<gD,256,GSMEM_TOTAL>>>(rh,rl,Wdech,Wdecl, nullptr,nullptr,nullptr,nullptr,
                                        b_dec,nullptr,nullptr, nullptr,hdh,hdl, DMOD,DMOD,1);
    // 11) out = hd @ W_out^T + b_out -> fp32 (N=128)
    mma_gemm<0><<<gO,256,GSMEM_TOTAL>>>(hdh,hdl,Wouth,Woutl, nullptr,nullptr,nullptr,nullptr,
                                        b_out,nullptr,nullptr, out,nullptr,nullptr, HIN,DMOD,1);
}

// round 17
// speedup vs baseline: 2.8085x; 1.0854x over previous
#include <cuda_runtime.h>
#include <cuda_bf16.h>
#include <math.h>
#include <stdint.h>

#define MTOT 16384   // B*L
#define DMOD 512
#define HIN  128
#define LSEQ 2048

typedef __nv_bfloat16 bf16;

// ---------------- scratch (static device globals: allocation-free) ----------------
__device__ float g_skip[MTOT*DMOD];
__device__ float g_hn  [MTOT*DMOD];
__device__ float g_bu  [MTOT*1024];     // [.,0:512)=Bu_re  [.,512:1024)=Bu_im
__device__ float g_gg  [MTOT*1024];     // [.,0:512)=g1     [.,512:1024)=g2
__device__ float g_bglu[1024];          // concat glu_b1 || glu_b2

__device__ bf16 g_xh [MTOT*HIN],  g_xl [MTOT*HIN];
__device__ bf16 g_h1h[MTOT*DMOD], g_h1l[MTOT*DMOD];
__device__ bf16 g_hnh[MTOT*DMOD], g_hnl[MTOT*DMOD];
__device__ bf16 g_xsrh[MTOT*DMOD], g_xsrl[MTOT*DMOD];
__device__ bf16 g_xsih[MTOT*DMOD], g_xsil[MTOT*DMOD];
__device__ bf16 g_yh [MTOT*DMOD], g_yl [MTOT*DMOD];
__device__ bf16 g_rh [MTOT*DMOD], g_rl [MTOT*DMOD];
__device__ bf16 g_hdh[MTOT*DMOD], g_hdl[MTOT*DMOD];

// weight hi/lo pairs
__device__ bf16 g_Winh [DMOD*HIN],   g_Winl [DMOD*HIN];
__device__ bf16 g_Wench[DMOD*DMOD],  g_Wencl[DMOD*DMOD];
__device__ bf16 g_Bcath[1024*DMOD],  g_Bcatl[1024*DMOD];   // B_re rows 0-511, B_im rows 512-1023
__device__ bf16 g_Creh [DMOD*DMOD],  g_Crel [DMOD*DMOD];
__device__ bf16 g_Cimh [DMOD*DMOD],  g_Ciml [DMOD*DMOD];   // pre-negated
__device__ bf16 g_Wgh  [1024*DMOD],  g_Wgl  [1024*DMOD];   // glu_w1 rows 0-511, glu_w2 rows 512-1023
__device__ bf16 g_Wdech[DMOD*DMOD],  g_Wdecl[DMOD*DMOD];
__device__ bf16 g_Wouth[HIN*DMOD],   g_Woutl[HIN*DMOD];

__device__ __forceinline__ float gelu_f(float x){
    float x3 = x*x*x;
    float t = tanhf(0.7978845608028654f*(x + 0.044715f*x3));
    return 0.5f*x*(1.0f+t);
}
__device__ __forceinline__ float sigmoid_f(float x){ return 1.0f/(1.0f+expf(-x)); }
__device__ __forceinline__ void split_bf16(float v, bf16& h, bf16& l){
    h = __float2bfloat16(v);
    l = __float2bfloat16(v - __bfloat162float(h));
}
__device__ __forceinline__ uint32_t pack_b2(bf16 a, bf16 b){
    uint16_t ua = *(uint16_t*)&a, ub = *(uint16_t*)&b;
    return (uint32_t)ua | ((uint32_t)ub << 16);
}
__device__ __forceinline__ uint32_t smem_u32(const void* p){
    uint32_t a;
    asm("{ .reg .u64 t; cvta.to.shared.u64 t, %1; cvt.u32.u64 %0, t; }" : "=r"(a) : "l"(p));
    return a;
}
__device__ __forceinline__ void cpa16(uint32_t dst, const void* src){
    asm volatile("cp.async.cg.shared.global [%0], [%1], 16;" :: "r"(dst), "l"(src));
}
__device__ __forceinline__ void cpa_commit(){ asm volatile("cp.async.commit_group;" ::: "memory"); }
__device__ __forceinline__ void ldm4(uint32_t addr, uint32_t& r0, uint32_t& r1,
                                     uint32_t& r2, uint32_t& r3){
    asm volatile("ldmatrix.sync.aligned.m8n8.x4.shared.b16 {%0,%1,%2,%3}, [%4];"
                 : "=r"(r0), "=r"(r1), "=r"(r2), "=r"(r3) : "r"(addr));
}
__device__ __forceinline__ void mma16816(float* d, const uint32_t* a,
                                         uint32_t b0, uint32_t b1){
    asm volatile("mma.sync.aligned.m16n8k16.row.col.f32.bf16.bf16.f32 "
                 "{%0,%1,%2,%3}, {%4,%5,%6,%7}, {%8,%9}, {%0,%1,%2,%3};"
                 : "+f"(d[0]), "+f"(d[1]), "+f"(d[2]), "+f"(d[3])
                 : "r"(a[0]), "r"(a[1]), "r"(a[2]), "r"(a[3]), "r"(b0), "r"(b1));
}

// ---------------- mma.sync GEMM with shared hi/lo tiles ----------------------------
// Per K-chunk (32): load Ah,Al,Bh,Bl once; accumulate Ah@Bh + Ah@Bl + Al@Bh.
// Single __syncthreads per chunk: next-chunk load is issued AFTER the barrier, so
// the destination buffer (used by chunk t-1) is provably free.
// EPI 0: fp32 out (+bias). EPI 1: bf16 hi/lo (+bias). EPI 2: gelu(acc+Dv*hn) -> hi/lo.
#define RS    80
#define TILEB (128*RS)              // 10240 per tile
#define STG   (4*TILEB)             // 40960 per stage (Ah,Al,Bh,Bl)
#define NSTG  2
#define GSMEM_TOTAL (NSTG*STG)      // 81920

template<int EPI>
__global__ __launch_bounds__(256,2)
void mma_gemm(const bf16* __restrict__ a1h, const bf16* __restrict__ a1l,
              const bf16* __restrict__ b1h, const bf16* __restrict__ b1l,
              const bf16* __restrict__ a2h, const bf16* __restrict__ a2l,
              const bf16* __restrict__ b2h, const bf16* __restrict__ b2l,
              const float* __restrict__ bias, const float* __restrict__ Dv,
              const float* __restrict__ hn,
              float* __restrict__ Yf, bf16* __restrict__ Yh, bf16* __restrict__ Yl,
              int N, int K, int npair)
{
    extern __shared__ __align__(128) char smem[];
    uint32_t sb = smem_u32(smem);
    const int tid = threadIdx.x, wid = tid>>5, lane = tid&31;
    const int warp_m = wid & 1, warp_n = wid >> 1;
    const int bm = blockIdx.y*128, bn = blockIdx.x*128;

    const bf16* AH[2] = {a1h, a2h};  const bf16* AL[2] = {a1l, a2l};
    const bf16* BH[2] = {b1h, b2h};  const bf16* BL[2] = {b1l, b2l};

    const int kcp = K >> 5;
    const int nch = npair * kcp;

    const int row = tid >> 1;
    const int cp2 = (tid & 1)*2;

    float acc[4][4][4];
    #pragma unroll
    for (int i=0;i<4;i++)
        #pragma unroll
        for (int j=0;j<4;j++){ acc[i][j][0]=0.f; acc[i][j][1]=0.f; acc[i][j][2]=0.f; acc[i][j][3]=0.f; }

    // chunk loader: 4 tiles (Ah, Al, Bh, Bl), 8 cp.async per thread
    auto load_chunk = [&](int t){
        int pr = t / kcp, kc = t - pr*kcp;
        uint32_t base = sb + (t & 1)*STG + row*RS + cp2*16;
        const bf16* s0 = AH[pr] + (size_t)(bm+row)*K + kc*32 + cp2*8;
        const bf16* s1 = AL[pr] + (size_t)(bm+row)*K + kc*32 + cp2*8;
        const bf16* s2 = BH[pr] + (size_t)(bn+row)*K + kc*32 + cp2*8;
        const bf16* s3 = BL[pr] + (size_t)(bn+row)*K + kc*32 + cp2*8;
        cpa16(base,            s0); cpa16(base+16,            s0+8);
        cpa16(base+  TILEB,    s1); cpa16(base+  TILEB+16,    s1+8);
        cpa16(base+2*TILEB,    s2); cpa16(base+2*TILEB+16,    s2+8);
        cpa16(base+3*TILEB,    s3); cpa16(base+3*TILEB+16,    s3+8);
    };

    load_chunk(0);
    cpa_commit();

    const int lrow = (lane & 7) + ((lane >> 3) & 1)*8;
    const int lcol = (lane >> 4)*16;

    for (int t=0; t<nch; t++){
        asm volatile("cp.async.wait_group 0;" ::: "memory");   // chunk t arrived
        __syncthreads();                                        // all warps done with chunk t-1
        if (t+1 < nch){
            load_chunk(t+1);                                    // overlaps compute of chunk t
            cpa_commit();
        }

        uint32_t ahb = sb + (t&1)*STG;
        uint32_t alb = ahb +   TILEB;
        uint32_t bhb = ahb + 2*TILEB;
        uint32_t blb = ahb + 3*TILEB;

        #pragma unroll
        for (int ks=0; ks<2; ks++){
            uint32_t koff = ks*32 + lcol;
            uint32_t ah[4][4], bh[2][4], bl[2][4];
            #pragma unroll
            for (int mt=0; mt<4; mt++)
                ldm4(ahb + (uint32_t)(warp_m*64 + mt*16 + lrow)*RS + koff,
                     ah[mt][0], ah[mt][1], ah[mt][2], ah[mt][3]);
            #pragma unroll
            for (int g=0; g<2; g++){
                ldm4(bhb + (uint32_t)(warp_n*32 + g*16 + lrow)*RS + koff,
                     bh[g][0], bh[g][1], bh[g][2], bh[g][3]);
                ldm4(blb + (uint32_t)(warp_n*32 + g*16 + lrow)*RS + koff,
                     bl[g][0], bl[g][1], bl[g][2], bl[g][3]);
            }
            // Ah@Bh and Ah@Bl
            #pragma unroll
            for (int mt=0; mt<4; mt++)
                #pragma unroll
                for (int nt=0; nt<4; nt++){
                    int g = nt >> 1, sub = nt & 1;
                    mma16816(acc[mt][nt], ah[mt], bh[g][sub], bh[g][sub+2]);
                    mma16816(acc[mt][nt], ah[mt], bl[g][sub], bl[g][sub+2]);
                }
            // Al@Bh (load al after bl is dead to cap register pressure)
            uint32_t al[4][4];
            #pragma unroll
            for (int mt=0; mt<4; mt++)
                ldm4(alb + (uint32_t)(warp_m*64 + mt*16 + lrow)*RS + koff,
                     al[mt][0], al[mt][1], al[mt][2], al[mt][3]);
            #pragma unroll
            for (int mt=0; mt<4; mt++)
                #pragma unroll
                for (int nt=0; nt<4; nt++){
                    int g = nt >> 1, sub = nt & 1;
                    mma16816(acc[mt][nt], al[mt], bh[g][sub], bh[g][sub+2]);
                }
        }
    }

    // ---------------- epilogue (packed 4B/8B stores; no smem use) ----------------
    const int r0l = lane >> 2;
    const int c0l = (lane & 3)*2;
    #pragma unroll
    for (int mt=0; mt<4; mt++){
        #pragma unroll
        for (int nt=0; nt<4; nt++){
            int colb = bn + warp_n*32 + nt*8 + c0l;
            #pragma unroll
            for (int h=0; h<2; h++){
                int rowg = bm + warp_m*64 + mt*16 + r0l + h*8;
                float v0 = acc[mt][nt][2*h+0];
                float v1 = acc[mt][nt][2*h+1];
                if (EPI==0){
                    if (bias){ v0 += bias[colb]; v1 += bias[colb+1]; }
                    float2 fv; fv.x = v0; fv.y = v1;
                    *(float2*)&Yf[(size_t)rowg*N + colb] = fv;
                } else if (EPI==1){
                    v0 += bias[colb]; v1 += bias[colb+1];
                    bf16 h0,l0,h1,l1;
                    split_bf16(v0,h0,l0); split_bf16(v1,h1,l1);
                    *(uint32_t*)&Yh[(size_t)rowg*N + colb] = pack_b2(h0,h1);
                    *(uint32_t*)&Yl[(size_t)rowg*N + colb] = pack_b2(l0,l1);
                } else {
                    v0 += Dv[colb]  *hn[(size_t)rowg*DMOD + colb];
                    v1 += Dv[colb+1]*hn[(size_t)rowg*DMOD + colb+1];
                    v0 = gelu_f(v0); v1 = gelu_f(v1);
                    bf16 h0,l0,h1,l1;
                    split_bf16(v0,h0,l0); split_bf16(v1,h1,l1);
                    *(uint32_t*)&Yh[(size_t)rowg*N + colb] = pack_b2(h0,h1);
                    *(uint32_t*)&Yl[(size_t)rowg*N + colb] = pack_b2(l0,l1);
                }
            }
        }
    }
}

// ---------------- batched fp32 -> bf16 hi/lo conversion (ALL inputs, 1 launch) -----
#define SZ_X   (MTOT*HIN)    // 2097152
#define SZ_DH  (DMOD*HIN)    // 65536
#define SZ_DD  (DMOD*DMOD)   // 262144
__global__ __launch_bounds__(256)
void conv_all(const float* __restrict__ x,    const float* __restrict__ W_in,
              const float* __restrict__ W_enc,const float* __restrict__ B_re,
              const float* __restrict__ B_im, const float* __restrict__ C_re,
              const float* __restrict__ C_im, const float* __restrict__ w1,
              const float* __restrict__ w2,   const float* __restrict__ W_dec,
              const float* __restrict__ W_out,const float* __restrict__ gb1,
              const float* __restrict__ gb2)
{
    const int O0 = SZ_X;                 // x
    const int O1 = O0 + SZ_DH;           // W_in
    const int O2 = O1 + SZ_DD;           // W_enc
    const int O3 = O2 + SZ_DD;           // B_re
    const int O4 = O3 + SZ_DD;           // B_im
    const int O5 = O4 + SZ_DD;           // C_re
    const int O6 = O5 + SZ_DD;           // C_im (negated)
    const int O7 = O6 + SZ_DD;           // w1
    const int O8 = O7 + SZ_DD;           // w2
    const int O9 = O8 + SZ_DD;           // W_dec
    const int O10= O9 + SZ_DH;           // W_out
    const int TOT= O10 + 1024;           // bias concat

    int i = blockIdx.x*256 + threadIdx.x;
    if (i >= TOT) return;
    if (i >= O10){                       // GLU bias concat (fp32 copy)
        int k = i - O10;
        g_bglu[k] = (k < 512) ? gb1[k] : gb2[k-512];
        return;
    }
    const float* src; bf16 *dh, *dl; int off; float sc = 1.0f;
    if      (i < O0){ src=x;     dh=g_xh;    dl=g_xl;    off=i;    }
    else if (i < O1){ src=W_in;  dh=g_Winh;  dl=g_Winl;  off=i-O0; }
    else if (i < O2){ src=W_enc; dh=g_Wench; dl=g_Wencl; off=i-O1; }
    else if (i < O3){ src=B_re;  dh=g_Bcath; dl=g_Bcatl; off=i-O2; }
    else if (i < O4){ src=B_im;  dh=g_Bcath+SZ_DD; dl=g_Bcatl+SZ_DD; off=i-O3; }
    else if (i < O5){ src=C_re;  dh=g_Creh;  dl=g_Crel;  off=i-O4; }
    else if (i < O6){ src=C_im;  dh=g_Cimh;  dl=g_Ciml;  off=i-O5; sc=-1.0f; }
    else if (i < O7){ src=w1;    dh=g_Wgh;   dl=g_Wgl;   off=i-O6; }
    else if (i < O8){ src=w2;    dh=g_Wgh+SZ_DD; dl=g_Wgl+SZ_DD; off=i-O7; }
    else if (i < O9){ src=W_dec; dh=g_Wdech; dl=g_Wdecl; off=i-O8; }
    else            { src=W_out; dh=g_Wouth; dl=g_Woutl; off=i-O9; }
    float v = src[off]*sc;
    bf16 h,l; split_bf16(v,h,l);
    dh[off]=h; dl[off]=l;
}

// ---------------- LayerNorm: fp32 out + bf16 hi/lo out -----------------------------
__global__ __launch_bounds__(128)
void ln_k(const float* __restrict__ X, const float* __restrict__ g,
          const float* __restrict__ b, float* __restrict__ Y,
          bf16* __restrict__ Yh, bf16* __restrict__ Yl)
{
    int row = blockIdx.x;
    const float4* x4 = (const float4*)(X + (size_t)row*DMOD);
    float4 v = x4[threadIdx.x];
    float s  = v.x+v.y+v.z+v.w;
    float s2 = v.x*v.x+v.y*v.y+v.z*v.z+v.w*v.w;
    #pragma unroll
    for (int o=16;o>0;o>>=1){
        s  += __shfl_xor_sync(0xffffffffu, s , o);
        s2 += __shfl_xor_sync(0xffffffffu, s2, o);
    }
    __shared__ float ss[4], ss2[4];
    int w = threadIdx.x >> 5;
    if ((threadIdx.x & 31)==0){ ss[w]=s; ss2[w]=s2; }
    __syncthreads();
    s  = ss[0]+ss[1]+ss[2]+ss[3];
    s2 = ss2[0]+ss2[1]+ss2[2]+ss2[3];
    float mean = s * (1.0f/DMOD);
    float var  = s2 * (1.0f/DMOD) - mean*mean;
    float inv  = rsqrtf(var + 1e-5f);
    float4 gg = ((const float4*)g)[threadIdx.x];
    float4 bb = ((const float4*)b)[threadIdx.x];
    float o0 = (v.x-mean)*inv*gg.x + bb.x;
    float o1 = (v.y-mean)*inv*gg.y + bb.y;
    float o2 = (v.z-mean)*inv*gg.z + bb.z;
    float o3 = (v.w-mean)*inv*gg.w + bb.w;
    float4 of; of.x=o0; of.y=o1; of.z=o2; of.w=o3;
    ((float4*)(Y + (size_t)row*DMOD))[threadIdx.x] = of;
    size_t bo = (size_t)row*DMOD + threadIdx.x*4;
    bf16 h0,l0,h1,l1;
    split_bf16(o0,h0,l0); split_bf16(o1,h1,l1);
    *(uint32_t*)&Yh[bo+0] = pack_b2(h0,h1);
    *(uint32_t*)&Yl[bo+0] = pack_b2(l0,l1);
    split_bf16(o2,h0,l0); split_bf16(o3,h1,l1);
    *(uint32_t*)&Yh[bo+2] = pack_b2(h0,h1);
    *(uint32_t*)&Yl[bo+2] = pack_b2(l0,l1);
}

// ---------------- LinOSS IM scan (reads fused g_bu layout, stride 1024) ------------
__global__ __launch_bounds__(128)
void scan_k(const float* __restrict__ bu,
            bf16* __restrict__ xsrh, bf16* __restrict__ xsrl,
            bf16* __restrict__ xsih, bf16* __restrict__ xsil,
            const float* __restrict__ A_diag, const float* __restrict__ log_steps)
{
    int idx  = blockIdx.x*128 + threadIdx.x;   // 0..8191
    int n    = idx & 511;
    int b    = (idx >> 9) & 7;
    int part = idx >> 12;                      // 0 real, 1 imag

    float A   = fmaxf(A_diag[n], 0.0f);
    float dt  = sigmoid_f(log_steps[n]);
    float dtA = dt*dt*A;
    float S   = 1.0f/(1.0f+dtA);
    float m11 = 1.0f - dtA*S;
    float m12 = -dt*A*S;
    float m21 = dt*S;
    float m22 = S;
    float cz  = m11*dt;
    float cx  = m21*dt;

    const float* src = bu + (size_t)b*LSEQ*1024 + part*512 + n;
    bf16* xh = (part ? xsih : xsrh) + (size_t)b*LSEQ*DMOD + n;
    bf16* xl = (part ? xsil : xsrl) + (size_t)b*LSEQ*DMOD + n;

    float z = 0.0f, x = 0.0f;
    for (int l0=0; l0<LSEQ; l0+=8){
        float v[8];
        #pragma unroll
        for (int u=0;u<8;u++) v[u] = __ldg(&src[(size_t)(l0+u)*1024]);
        #pragma unroll
        for (int u=0;u<8;u++){
            float zn = fmaf(m11, z, fmaf(m12, x, cz*v[u]));
            float xn = fmaf(m21, z, fmaf(m22, x, cx*v[u]));
            z = zn; x = xn;
            bf16 h,l; split_bf16(x,h,l);
            xh[(size_t)(l0+u)*DMOD] = h;
            xl[(size_t)(l0+u)*DMOD] = l;
        }
    }
}

// ---------------- GLU + residual (reads fused g_gg layout) -------------------------
__global__ __launch_bounds__(256)
void glu_res_k(const float* __restrict__ skip, const float* __restrict__ gg,
               bf16* __restrict__ rh, bf16* __restrict__ rl, int n4)
{
    int i = blockIdx.x*blockDim.x + threadIdx.x;
    if (i >= n4) return;
    int row  = (i*4) >> 9;          // /512
    int col4 = (i*4) & 511;
    float4 s  = *(const float4*)(skip + (size_t)row*512  + col4);
    float4 av = *(const float4*)(gg   + (size_t)row*1024 + col4);
    float4 gv = *(const float4*)(gg   + (size_t)row*1024 + 512 + col4);
    float o0 = s.x + av.x*sigmoid_f(gv.x);
    float o1 = s.y + av.y*sigmoid_f(gv.y);
    float o2 = s.z + av.z*sigmoid_f(gv.z);
    float o3 = s.w + av.w*sigmoid_f(gv.w);
    size_t bo = (size_t)row*512 + col4;
    bf16 h0,l0,h1,l1;
    split_bf16(o0,h0,l0); split_bf16(o1,h1,l1);
    *(uint32_t*)&rh[bo+0] = pack_b2(h0,h1);
    *(uint32_t*)&rl[bo+0] = pack_b2(l0,l1);
    split_bf16(o2,h0,l0); split_bf16(o3,h1,l1);
    *(uint32_t*)&rh[bo+2] = pack_b2(h0,h1);
    *(uint32_t*)&rl[bo+2] = pack_b2(l0,l1);
}

// ---------------- host launcher ----------------------------------------------------
static float* symf(const void* s){ void* p=nullptr; cudaGetSymbolAddress(&p, s); return (float*)p; }
static bf16*  symb(const void* s){ void* p=nullptr; cudaGetSymbolAddress(&p, s); return (bf16*)p; }

extern "C" void kernel_launch(void* const* d_in, const int* in_sizes, int n_in,
                              void* d_out, int out_size)
{
    const float* x      = (const float*)d_in[0];
    const float* W_in   = (const float*)d_in[1];
    const float* b_in   = (const float*)d_in[2];
    const float* W_enc  = (const float*)d_in[3];
    const float* b_enc  = (const float*)d_in[4];
    const float* ln_g   = (const float*)d_in[5];
    const float* ln_b   = (const float*)d_in[6];
    const float* A_diag = (const float*)d_in[7];
    const float* log_st = (const float*)d_in[8];
    const float* B_re   = (const float*)d_in[9];
    const float* B_im   = (const float*)d_in[10];
    const float* C_re   = (const float*)d_in[11];
    const float* C_im   = (const float*)d_in[12];
    const float* Dvec   = (const float*)d_in[13];
    const float* glu_w1 = (const float*)d_in[14];
    const float* glu_b1 = (const float*)d_in[15];
    const float* glu_w2 = (const float*)d_in[16];
    const float* glu_b2 = (const float*)d_in[17];
    const float* W_dec  = (const float*)d_in[18];
    const float* b_dec  = (const float*)d_in[19];
    const float* W_out  = (const float*)d_in[20];
    const float* b_out  = (const float*)d_in[21];
    float* out = (float*)d_out;

    float* skip = symf(g_skip); float* hn = symf(g_hn);
    float* bu   = symf(g_bu);   float* gg = symf(g_gg);
    float* bglu = symf(g_bglu);

    bf16 *xh=symb(g_xh), *xl=symb(g_xl);
    bf16 *h1h=symb(g_h1h), *h1l=symb(g_h1l);
    bf16 *hnh=symb(g_hnh), *hnl=symb(g_hnl);
    bf16 *xsrh=symb(g_xsrh), *xsrl=symb(g_xsrl);
    bf16 *xsih=symb(g_xsih), *xsil=symb(g_xsil);
    bf16 *yh=symb(g_yh), *yl=symb(g_yl);
    bf16 *rh=symb(g_rh), *rl=symb(g_rl);
    bf16 *hdh=symb(g_hdh), *hdl=symb(g_hdl);
    bf16 *Winh=symb(g_Winh), *Winl=symb(g_Winl);
    bf16 *Wench=symb(g_Wench), *Wencl=symb(g_Wencl);
    bf16 *Bcath=symb(g_Bcath), *Bcatl=symb(g_Bcatl);
    bf16 *Creh=symb(g_Creh), *Crel=symb(g_Crel);
    bf16 *Cimh=symb(g_Cimh), *Ciml=symb(g_Ciml);
    bf16 *Wgh=symb(g_Wgh), *Wgl=symb(g_Wgl);
    bf16 *Wdech=symb(g_Wdech), *Wdecl=symb(g_Wdecl);
    bf16 *Wouth=symb(g_Wouth), *Woutl=symb(g_Woutl);

    cudaFuncSetAttribute(mma_gemm<0>, cudaFuncAttributeMaxDynamicSharedMemorySize, GSMEM_TOTAL);
    cudaFuncSetAttribute(mma_gemm<1>, cudaFuncAttributeMaxDynamicSharedMemorySize, GSMEM_TOTAL);
    cudaFuncSetAttribute(mma_gemm<2>, cudaFuncAttributeMaxDynamicSharedMemorySize, GSMEM_TOTAL);

    // 1) all conversions, one launch
    const int TOT_CONV = SZ_X + 2*SZ_DH + 8*SZ_DD + 1024;
    conv_all<<<(TOT_CONV+255)/256,256>>>(x, W_in, W_enc, B_re, B_im, C_re, C_im,
                                         glu_w1, glu_w2, W_dec, W_out, glu_b1, glu_b2);

    dim3 gD (DMOD/128, MTOT/128);   // (4,128)
    dim3 gD2(1024/128, MTOT/128);   // (8,128) fused dual-weight
    dim3 gO (HIN /128, MTOT/128);   // (1,128)

    // 2) h1 = x @ W_in^T + b_in  -> bf16 pair   (K=128)
    mma_gemm<1><<<gD,256,GSMEM_TOTAL>>>(xh,xl,Winh,Winl, nullptr,nullptr,nullptr,nullptr,
                                        b_in,nullptr,nullptr, nullptr,h1h,h1l, DMOD,HIN,1);
    // 3) skip = h1 @ W_enc^T + b_enc -> fp32
    mma_gemm<0><<<gD,256,GSMEM_TOTAL>>>(h1h,h1l,Wench,Wencl, nullptr,nullptr,nullptr,nullptr,
                                        b_enc,nullptr,nullptr, skip,nullptr,nullptr, DMOD,DMOD,1);
    // 4) hn = LN(skip)
    ln_k<<<MTOT,128>>>(skip, ln_g, ln_b, hn, hnh, hnl);
    // 5) bu = hn @ [B_re;B_im]^T  -> fp32, N=1024 (fused re+im)
    mma_gemm<0><<<gD2,256,GSMEM_TOTAL>>>(hnh,hnl,Bcath,Bcatl, nullptr,nullptr,nullptr,nullptr,
                                         nullptr,nullptr,nullptr, bu,nullptr,nullptr, 1024,DMOD,1);
    // 6) scan -> xs (bf16 pairs)
    scan_k<<<64,128>>>(bu, xsrh, xsrl, xsih, xsil, A_diag, log_st);
    // 7) y = gelu(xsr@C_re^T - xsi@C_im^T + D*hn) -> bf16 pair (npair=2)
    mma_gemm<2><<<gD,256,GSMEM_TOTAL>>>(xsrh,xsrl,Creh,Crel, xsih,xsil,Cimh,Ciml,
                                        nullptr,Dvec,hn, nullptr,yh,yl, DMOD,DMOD,2);
    // 8) gg = y @ [w1;w2]^T + [b1;b2] -> fp32, N=1024 (fused GLU branches)
    mma_gemm<0><<<gD2,256,GSMEM_TOTAL>>>(yh,yl,Wgh,Wgl, nullptr,nullptr,nullptr,nullptr,
                                         bglu,nullptr,nullptr, gg,nullptr,nullptr, 1024,DMOD,1);
    // 9) r = skip + g1*sigmoid(g2) -> bf16 pair
    int n4 = MTOT*DMOD/4;
    glu_res_k<<<(n4+255)/256,256>>>(skip, gg, rh, rl, n4);
    // 10) hd = r @ W_dec^T + b_dec -> bf16 pair
    mma_gemm<1><<<gD,256,GSMEM_TOTAL>>>(rh,rl,Wdech,Wdecl, nullptr,nullptr,nullptr,nullptr,
                                        b_dec,nullptr,nullptr, nullptr,hdh,hdl, DMOD,DMOD,1);
    // 11) out = hd @ W_out^T + b_out -> fp32 (N=128)
    mma_gemm<0><<<gO,256,GSMEM_TOTAL>>>(hdh,hdl,Wouth,Woutl, nullptr,nullptr,nullptr,nullptr,
                                        b_out,nullptr,nullptr, out,nullptr,nullptr, HIN,DMOD,1);
}